// round 1
// baseline (speedup 1.0000x reference)
#include <cuda_runtime.h>
#include <math.h>
#include <stdint.h>

#define BIGF 1e10f
#define NMAX 3072
#define KMAXG 64
#define TI 16

// Scratch (no allocations allowed): distance matrix + edge index staging.
__device__ float g_dist[(size_t)NMAX * NMAX];          // ~37.7 MB
__device__ int g_dst[NMAX * KMAXG];
__device__ int g_src[NMAX * KMAXG];
__device__ unsigned char g_val[NMAX * KMAXG];

// ---------------------------------------------------------------------------
// Kernel 1: node features H[i, 0:E] = res_embed[S[i]],
//           H[i, E:2E] = sinusoidal(RP[i]) + id_embed[ID[i]]
// ---------------------------------------------------------------------------
__global__ void node_feat_kernel(const float* __restrict__ res_embed,
                                 const float* __restrict__ id_embed,
                                 const int* __restrict__ S,
                                 const int* __restrict__ RP,
                                 const int* __restrict__ ID,
                                 float* __restrict__ out, int N, int E) {
  int i = blockIdx.x;
  int t = threadIdx.x;           // 0 .. 2E-1
  if (i >= N || t >= 2 * E) return;
  float v;
  if (t < E) {
    v = res_embed[S[i] * E + t];
  } else {
    int j = t - E;
    int p = j >> 1;
    // freq = 10000^(-2*p/E)
    float freq = powf(10000.0f, -2.0f * (float)p / (float)E);
    float ang = (float)RP[i] * freq;
    v = (j & 1) ? cosf(ang) : sinf(ang);   // interleaved sin/cos
    v += id_embed[ID[i] * E + j];
  }
  out[(size_t)i * (2 * E) + t] = v;
}

// ---------------------------------------------------------------------------
// Kernel 2: masked pairwise min-over-channel-pair distance matrix.
// dist[i][j] = rule ? sqrt(max(min_{c,e} (sq_i_c + sq_j_e - 2*dot), 0)) : 1e10
// ---------------------------------------------------------------------------
__global__ void dist_kernel(const float* __restrict__ X,
                            const int* __restrict__ Seg,
                            const int* __restrict__ bid, int N) {
  __shared__ float sXi[TI][12];
  __shared__ float sSq[TI][4];
  __shared__ int sB[TI], sS[TI];
  int i0 = blockIdx.x * TI;
  int t = threadIdx.x;

  for (int idx = t; idx < TI * 12; idx += blockDim.x) {
    int r = idx / 12, c = idx % 12;
    int gi = i0 + r;
    sXi[r][c] = (gi < N) ? X[(size_t)gi * 12 + c] : 0.0f;
  }
  __syncthreads();
  if (t < TI) {
    int gi = i0 + t;
    if (gi < N) {
      sB[t] = bid[gi];
      sS[t] = Seg[gi];
      for (int c = 0; c < 4; c++) {
        float x = sXi[t][c * 3 + 0];
        float y = sXi[t][c * 3 + 1];
        float z = sXi[t][c * 3 + 2];
        sSq[t][c] = x * x + y * y + z * z;
      }
    }
  }
  __syncthreads();

  int ilim = min(TI, N - i0);
  for (int j = t; j < N; j += blockDim.x) {
    // X[j] = 12 consecutive floats, 16B-aligned (48B stride)
    const float4* xp = (const float4*)(X + (size_t)j * 12);
    float4 a = xp[0], b = xp[1], c4 = xp[2];
    float xj[4][3] = {{a.x, a.y, a.z},
                      {a.w, b.x, b.y},
                      {b.z, b.w, c4.x},
                      {c4.y, c4.z, c4.w}};
    float sqj[4];
#pragma unroll
    for (int e = 0; e < 4; e++)
      sqj[e] = xj[e][0] * xj[e][0] + xj[e][1] * xj[e][1] + xj[e][2] * xj[e][2];
    int bj = bid[j], sj = Seg[j];

    for (int r = 0; r < ilim; r++) {
      float best = 3.4e38f;
#pragma unroll
      for (int c = 0; c < 4; c++) {
        float xi0 = sXi[r][c * 3 + 0];
        float xi1 = sXi[r][c * 3 + 1];
        float xi2 = sXi[r][c * 3 + 2];
        float sic = sSq[r][c];
#pragma unroll
        for (int e = 0; e < 4; e++) {
          float dot = xi0 * xj[e][0] + xi1 * xj[e][1] + xi2 * xj[e][2];
          float d2 = sic + sqj[e] - 2.0f * dot;
          best = fminf(best, d2);
        }
      }
      float d = (sB[r] == bj && sS[r] == sj) ? sqrtf(fmaxf(best, 0.0f)) : BIGF;
      g_dist[(size_t)(i0 + r) * N + j] = d;
    }
  }
}

// ---------------------------------------------------------------------------
// Kernel 3: top-k=10 smallest per row with jax.lax.top_k tie semantics.
// Key = (float_bits << 32) | j  — non-negative floats sort by bit pattern,
// ties broken by ascending index. One warp per row.
// ---------------------------------------------------------------------------
__global__ void topk10_kernel(int N, float* __restrict__ out,
                              size_t offE, size_t offV) {
  const int K = 10;
  int i = blockIdx.x;
  int lane = threadIdx.x;  // blockDim = 32
  const float* row = g_dist + (size_t)i * N;

  unsigned long long loc[K];
#pragma unroll
  for (int m = 0; m < K; m++) loc[m] = ~0ull;

  for (int j = lane; j < N; j += 32) {
    unsigned long long key =
        ((unsigned long long)__float_as_uint(row[j]) << 32) | (unsigned int)j;
    if (key < loc[K - 1]) {
      loc[K - 1] = key;
#pragma unroll
      for (int m = K - 1; m > 0; m--) {
        if (loc[m] < loc[m - 1]) {
          unsigned long long tmp = loc[m];
          loc[m] = loc[m - 1];
          loc[m - 1] = tmp;
        }
      }
    }
  }

  __shared__ unsigned long long sh[32 * K];
#pragma unroll
  for (int m = 0; m < K; m++) sh[lane * K + m] = loc[m];
  __syncwarp();

  for (int h = 16; h >= 1; h >>= 1) {
    if (lane < h) {
      unsigned long long mg[K];
      int p = 0, q = 0;
#pragma unroll
      for (int m = 0; m < K; m++) {
        unsigned long long av = sh[lane * K + p];
        unsigned long long bv = sh[(lane + h) * K + q];
        if (av <= bv) { mg[m] = av; p++; }
        else          { mg[m] = bv; q++; }
      }
#pragma unroll
      for (int m = 0; m < K; m++) sh[lane * K + m] = mg[m];
    }
    __syncwarp();
  }

  if (lane < K) {
    unsigned long long key = sh[lane];
    unsigned int j = (unsigned int)key;
    float v = __uint_as_float((unsigned int)(key >> 32));
    bool valid = (v < BIGF);
    int e = i * K + lane;
    out[offE + e] = valid ? (float)j : -1.0f;                 // edges[0] (dst)
    out[offE + (size_t)N * K + e] = valid ? (float)i : -1.0f; // edges[1] (src)
    out[offV + e] = valid ? 1.0f : 0.0f;                      // valid mask
    g_dst[e] = valid ? (int)j : 0;   // max(edge, 0)
    g_src[e] = valid ? i : 0;
    g_val[e] = valid ? 1 : 0;
  }
}

// Generic fallback for k != 10 (one thread per row, local-memory list).
__global__ void topk_generic_kernel(int N, int k, float* __restrict__ out,
                                    size_t offE, size_t offV) {
  int i = blockIdx.x * blockDim.x + threadIdx.x;
  if (i >= N) return;
  unsigned long long loc[KMAXG];
  for (int m = 0; m < k; m++) loc[m] = ~0ull;
  const float* row = g_dist + (size_t)i * N;
  for (int j = 0; j < N; j++) {
    unsigned long long key =
        ((unsigned long long)__float_as_uint(row[j]) << 32) | (unsigned int)j;
    if (key < loc[k - 1]) {
      loc[k - 1] = key;
      for (int m = k - 1; m > 0; m--) {
        if (loc[m] < loc[m - 1]) {
          unsigned long long tmp = loc[m];
          loc[m] = loc[m - 1];
          loc[m - 1] = tmp;
        }
      }
    }
  }
  for (int m = 0; m < k; m++) {
    unsigned long long key = loc[m];
    unsigned int j = (unsigned int)key;
    float v = __uint_as_float((unsigned int)(key >> 32));
    bool valid = (v < BIGF);
    int e = i * k + m;
    out[offE + e] = valid ? (float)j : -1.0f;
    out[offE + (size_t)N * k + e] = valid ? (float)i : -1.0f;
    out[offV + e] = valid ? 1.0f : 0.0f;
    g_dst[e] = valid ? (int)j : 0;
    g_src[e] = valid ? i : 0;
    g_val[e] = valid ? 1 : 0;
  }
}

// ---------------------------------------------------------------------------
// Kernel 4: pairwise dihedrals on backbone atoms.
// ---------------------------------------------------------------------------
__device__ __forceinline__ float3 ldatom(const float* __restrict__ X, int n, int c) {
  const float* p = X + (size_t)n * 12 + c * 3;
  return make_float3(p[0], p[1], p[2]);
}
__device__ __forceinline__ float3 f3sub(float3 a, float3 b) {
  return make_float3(a.x - b.x, a.y - b.y, a.z - b.z);
}
__device__ __forceinline__ float3 f3cross(float3 a, float3 b) {
  return make_float3(a.y * b.z - a.z * b.y,
                     a.z * b.x - a.x * b.z,
                     a.x * b.y - a.y * b.x);
}
__device__ __forceinline__ float f3dot(float3 a, float3 b) {
  return a.x * b.x + a.y * b.y + a.z * b.z;
}
__device__ __forceinline__ float dihedral4(float3 a, float3 b, float3 c, float3 d) {
  float3 u1 = f3sub(b, a), u2 = f3sub(c, b), u3 = f3sub(d, c);
  float3 n1 = f3cross(u1, u2), n2 = f3cross(u2, u3);
  float nrm = sqrtf(f3dot(u2, u2)) + 1e-12f;
  float3 u2n = make_float3(u2.x / nrm, u2.y / nrm, u2.z / nrm);
  float3 m = f3cross(n1, u2n);
  float x = f3dot(n1, n2);
  float y = f3dot(m, n2);
  return atan2f(y, x);
}

__global__ void edge_attr_kernel(const float* __restrict__ X,
                                 float* __restrict__ out, size_t offA, int NE) {
  int e = blockIdx.x * blockDim.x + threadIdx.x;
  if (e >= NE) return;
  int dj = g_dst[e], si = g_src[e];
  float3 dN = ldatom(X, dj, 0), dCA = ldatom(X, dj, 1), dC = ldatom(X, dj, 2);
  float3 sN = ldatom(X, si, 0), sCA = ldatom(X, si, 1), sC = ldatom(X, si, 2);
  // ir_phi = dihedral(C_i, N_j, CA_j, C_j)  (i = dst, j = src per reference)
  float phi = dihedral4(dC, sN, sCA, sC);
  // ir_psi = dihedral(N_i, CA_i, C_i, N_j)
  float psi = dihedral4(dN, dCA, dC, sN);
  bool v = (g_val[e] != 0);
  out[offA + 2 * (size_t)e + 0] = v ? phi : 0.0f;
  out[offA + 2 * (size_t)e + 1] = v ? psi : 0.0f;
}

// ---------------------------------------------------------------------------
// Launcher. Output = concat(H[N,2E], edges[2,N*k], edge_attr[N*k,2], valid[N*k])
// flattened as float32.
// ---------------------------------------------------------------------------
extern "C" void kernel_launch(void* const* d_in, const int* in_sizes, int n_in,
                              void* d_out, int out_size) {
  const float* X = (const float*)d_in[0];
  const int* S = (const int*)d_in[1];
  const int* RP = (const int*)d_in[2];
  const int* ID = (const int*)d_in[3];
  const int* Seg = (const int*)d_in[4];
  const int* bid = (const int*)d_in[5];
  const float* res_embed = (const float*)d_in[6];
  const float* id_embed = (const float*)d_in[7];
  float* out = (float*)d_out;

  int N = in_sizes[0] / 12;       // X is [N,4,3]
  int E = in_sizes[7] / 2;        // id_embed is [2,E]
  // out_size = N*2E + 5*N*k  ->  k
  long long rem = (long long)out_size - 2LL * E * N;
  int k = (int)(rem / (5LL * N));
  if (k < 1) k = 1;
  if (k > KMAXG) k = KMAXG;

  size_t offE = (size_t)N * 2 * E;             // edges start
  size_t offA = offE + (size_t)2 * N * k;      // edge_attr start
  size_t offV = offA + (size_t)2 * N * k;      // valid start

  node_feat_kernel<<<N, 2 * E>>>(res_embed, id_embed, S, RP, ID, out, N, E);
  dist_kernel<<<(N + TI - 1) / TI, 256>>>(X, Seg, bid, N);
  if (k == 10) {
    topk10_kernel<<<N, 32>>>(N, out, offE, offV);
  } else {
    topk_generic_kernel<<<(N + 63) / 64, 64>>>(N, k, out, offE, offV);
  }
  edge_attr_kernel<<<(N * k + 127) / 128, 128>>>(X, out, offA, N * k);
}

// round 2
// speedup vs baseline: 1.6814x; 1.6814x over previous
#include <cuda_runtime.h>
#include <math.h>
#include <stdint.h>

#define BIGF 1e10f
#define NMAX 3072
#define KMAXG 64
#define TI 16
#define TJ 512
#define TJP 513

// Scratch (no allocations allowed).
__device__ float g_dist[(size_t)NMAX * NMAX];          // ~37.7 MB (L2-resident)
__device__ int g_dst[NMAX * KMAXG];
__device__ int g_src[NMAX * KMAXG];
__device__ unsigned char g_val[NMAX * KMAXG];

// ---------------------------------------------------------------------------
// Packed f32x2 helpers (Blackwell FFMA2 path — PTX only, ptxas won't auto-fuse)
// ---------------------------------------------------------------------------
static __device__ __forceinline__ unsigned long long pk2(float a, float b) {
  unsigned long long r;
  asm("mov.b64 %0, {%1,%2};" : "=l"(r) : "f"(a), "f"(b));
  return r;
}
static __device__ __forceinline__ void upk2(unsigned long long v, float& a, float& b) {
  asm("mov.b64 {%0,%1}, %2;" : "=f"(a), "=f"(b) : "l"(v));
}
static __device__ __forceinline__ unsigned long long fma2_(unsigned long long a,
                                                           unsigned long long b,
                                                           unsigned long long c) {
  unsigned long long r;
  asm("fma.rn.f32x2 %0, %1, %2, %3;" : "=l"(r) : "l"(a), "l"(b), "l"(c));
  return r;
}
static __device__ __forceinline__ unsigned long long mul2_(unsigned long long a,
                                                           unsigned long long b) {
  unsigned long long r;
  asm("mul.rn.f32x2 %0, %1, %2;" : "=l"(r) : "l"(a), "l"(b));
  return r;
}
static __device__ __forceinline__ unsigned long long add2_(unsigned long long a,
                                                           unsigned long long b) {
  unsigned long long r;
  asm("add.rn.f32x2 %0, %1, %2;" : "=l"(r) : "l"(a), "l"(b));
  return r;
}

// ---------------------------------------------------------------------------
// Kernel 1: node features
// ---------------------------------------------------------------------------
__global__ void node_feat_kernel(const float* __restrict__ res_embed,
                                 const float* __restrict__ id_embed,
                                 const int* __restrict__ S,
                                 const int* __restrict__ RP,
                                 const int* __restrict__ ID,
                                 float* __restrict__ out, int N, int E) {
  int i = blockIdx.x;
  int t = threadIdx.x;
  if (i >= N || t >= 2 * E) return;
  float v;
  if (t < E) {
    v = res_embed[S[i] * E + t];
  } else {
    int j = t - E;
    int p = j >> 1;
    float freq = powf(10000.0f, -2.0f * (float)p / (float)E);
    float ang = (float)RP[i] * freq;
    v = (j & 1) ? cosf(ang) : sinf(ang);
    v += id_embed[ID[i] * E + j];
  }
  out[(size_t)i * (2 * E) + t] = v;
}

// ---------------------------------------------------------------------------
// Kernel 2: symmetric masked pairwise min-channel distance, packed f32x2.
// Block = 16 i-rows x 512 j-cols (256 threads x 2 packed j). Computes only
// j >= i; mirrors the lower triangle through an smem transpose.
// ---------------------------------------------------------------------------
__global__ __launch_bounds__(256) void dist_kernel(const float* __restrict__ X,
                                                   const int* __restrict__ Seg,
                                                   const int* __restrict__ bid,
                                                   int N) {
  __shared__ unsigned long long sXip[TI][4][3];
  __shared__ unsigned long long sSicp[TI][4];
  __shared__ int sB[TI], sS[TI];
  __shared__ float sD[TI][TJP];

  int i0 = blockIdx.y * TI;
  int j0 = blockIdx.x * TJ;
  if (j0 + TJ - 1 < i0) return;  // tile fully below diagonal

  int t = threadIdx.x;
  if (t < TI * 4) {
    int r = t >> 2, c = t & 3;
    int gic = min(i0 + r, N - 1);
    const float* p = X + (size_t)gic * 12 + c * 3;
    float x = p[0], y = p[1], z = p[2];
    sXip[r][c][0] = pk2(x, x);
    sXip[r][c][1] = pk2(y, y);
    sXip[r][c][2] = pk2(z, z);
    float sic = x * x + y * y + z * z;
    sSicp[r][c] = pk2(sic, sic);
    if (c == 0) { sB[r] = bid[gic]; sS[r] = Seg[gic]; }
  }
  __syncthreads();

  int jA = j0 + 2 * t, jB = jA + 1;
  int jAc = min(jA, N - 1), jBc = min(jB, N - 1);
  const float4* pa = (const float4*)(X + (size_t)jAc * 12);
  const float4* pb = (const float4*)(X + (size_t)jBc * 12);
  float4 a0 = pa[0], a1 = pa[1], a2 = pa[2];
  float4 b0 = pb[0], b1 = pb[1], b2 = pb[2];
  float xa[12] = {a0.x, a0.y, a0.z, a0.w, a1.x, a1.y,
                  a1.z, a1.w, a2.x, a2.y, a2.z, a2.w};
  float xb[12] = {b0.x, b0.y, b0.z, b0.w, b1.x, b1.y,
                  b1.z, b1.w, b2.x, b2.y, b2.z, b2.w};
  unsigned long long xjp[4][3], sqjp[4];
#pragma unroll
  for (int e = 0; e < 4; e++) {
#pragma unroll
    for (int d = 0; d < 3; d++) xjp[e][d] = pk2(xa[e * 3 + d], xb[e * 3 + d]);
    sqjp[e] = fma2_(xjp[e][0], xjp[e][0],
                    fma2_(xjp[e][1], xjp[e][1], mul2_(xjp[e][2], xjp[e][2])));
  }
  int bidA = bid[jAc], segA = Seg[jAc];
  int bidB = bid[jBc], segB = Seg[jBc];
  const unsigned long long M2 = pk2(-2.0f, -2.0f);

  for (int r = 0; r < TI; r++) {
    int i = i0 + r;
    if (i >= N) break;
    if (jB < i) continue;  // both j strictly below diagonal: owned elsewhere
    float best0 = 3.4e38f, best1 = 3.4e38f;
#pragma unroll
    for (int c = 0; c < 4; c++) {
      unsigned long long xi0 = sXip[r][c][0];
      unsigned long long xi1 = sXip[r][c][1];
      unsigned long long xi2 = sXip[r][c][2];
      unsigned long long sic = sSicp[r][c];
#pragma unroll
      for (int e = 0; e < 4; e++) {
        unsigned long long dot =
            fma2_(xi0, xjp[e][0], fma2_(xi1, xjp[e][1], mul2_(xi2, xjp[e][2])));
        unsigned long long d2 = fma2_(dot, M2, add2_(sic, sqjp[e]));
        float d20, d21;
        upk2(d2, d20, d21);
        best0 = fminf(best0, d20);  // FMNMX -> alu pipe, overlaps fma pipe
        best1 = fminf(best1, d21);
      }
    }
    int bi_ = sB[r], si_ = sS[r];
    float d0 = (bi_ == bidA && si_ == segA) ? sqrtf(fmaxf(best0, 0.0f)) : BIGF;
    float d1 = (bi_ == bidB && si_ == segB) ? sqrtf(fmaxf(best1, 0.0f)) : BIGF;
    if (jA >= i && jA < N) g_dist[(size_t)i * N + jA] = d0;
    if (jB >= i && jB < N) g_dist[(size_t)i * N + jB] = d1;
    sD[r][2 * t] = d0;
    sD[r][2 * t + 1] = d1;
  }
  __syncthreads();

  // Mirror lower triangle: g_dist[j][i] = sD[i-i0][j-j0], predicate j > i.
  // 16 consecutive threads cover one j-row (64B contiguous stores); TJP=513
  // padding makes the sD column read conflict-free.
  for (int idx = t; idx < TI * TJ; idx += 256) {
    int jr = idx >> 4;
    int rr = idx & 15;
    int j = j0 + jr, i = i0 + rr;
    if (j < N && i < N && j > i) g_dist[(size_t)j * N + i] = sD[rr][jr];
  }
}

// ---------------------------------------------------------------------------
// Dihedral helpers
// ---------------------------------------------------------------------------
__device__ __forceinline__ float3 ldatom(const float* __restrict__ X, int n, int c) {
  const float* p = X + (size_t)n * 12 + c * 3;
  return make_float3(p[0], p[1], p[2]);
}
__device__ __forceinline__ float3 f3sub(float3 a, float3 b) {
  return make_float3(a.x - b.x, a.y - b.y, a.z - b.z);
}
__device__ __forceinline__ float3 f3cross(float3 a, float3 b) {
  return make_float3(a.y * b.z - a.z * b.y, a.z * b.x - a.x * b.z,
                     a.x * b.y - a.y * b.x);
}
__device__ __forceinline__ float f3dot(float3 a, float3 b) {
  return a.x * b.x + a.y * b.y + a.z * b.z;
}
__device__ __forceinline__ float dihedral4(float3 a, float3 b, float3 c, float3 d) {
  float3 u1 = f3sub(b, a), u2 = f3sub(c, b), u3 = f3sub(d, c);
  float3 n1 = f3cross(u1, u2), n2 = f3cross(u2, u3);
  float nrm = sqrtf(f3dot(u2, u2)) + 1e-12f;
  float3 u2n = make_float3(u2.x / nrm, u2.y / nrm, u2.z / nrm);
  float3 m = f3cross(n1, u2n);
  return atan2f(f3dot(m, n2), f3dot(n1, n2));
}

// ---------------------------------------------------------------------------
// Kernel 3: top-10 per row (jax.lax.top_k tie semantics) + fused dihedrals.
// One warp per row; packed (dist_bits<<32 | j) keys.
// ---------------------------------------------------------------------------
__global__ void topk10_kernel(const float* __restrict__ X, int N,
                              float* __restrict__ out, size_t offE,
                              size_t offA, size_t offV) {
  const int K = 10;
  int i = blockIdx.x;
  int lane = threadIdx.x;
  const float* row = g_dist + (size_t)i * N;

  unsigned long long loc[K];
#pragma unroll
  for (int m = 0; m < K; m++) loc[m] = ~0ull;

  for (int j = lane; j < N; j += 32) {
    unsigned long long key =
        ((unsigned long long)__float_as_uint(row[j]) << 32) | (unsigned int)j;
    if (key < loc[K - 1]) {
      loc[K - 1] = key;
#pragma unroll
      for (int m = K - 1; m > 0; m--) {
        if (loc[m] < loc[m - 1]) {
          unsigned long long tmp = loc[m];
          loc[m] = loc[m - 1];
          loc[m - 1] = tmp;
        }
      }
    }
  }

  __shared__ unsigned long long sh[32 * K];
#pragma unroll
  for (int m = 0; m < K; m++) sh[lane * K + m] = loc[m];
  __syncwarp();

  for (int h = 16; h >= 1; h >>= 1) {
    if (lane < h) {
      unsigned long long mg[K];
      int p = 0, q = 0;
#pragma unroll
      for (int m = 0; m < K; m++) {
        unsigned long long av = sh[lane * K + p];
        unsigned long long bv = sh[(lane + h) * K + q];
        if (av <= bv) { mg[m] = av; p++; }
        else          { mg[m] = bv; q++; }
      }
#pragma unroll
      for (int m = 0; m < K; m++) sh[lane * K + m] = mg[m];
    }
    __syncwarp();
  }

  if (lane < K) {
    unsigned long long key = sh[lane];
    unsigned int j = (unsigned int)key;
    float v = __uint_as_float((unsigned int)(key >> 32));
    bool valid = (v < BIGF);
    int e = i * K + lane;
    out[offE + e] = valid ? (float)j : -1.0f;                 // edges[0] (dst)
    out[offE + (size_t)N * K + e] = valid ? (float)i : -1.0f; // edges[1] (src)
    out[offV + e] = valid ? 1.0f : 0.0f;                      // valid mask

    // fused dihedrals: dst = max(edge,0) = j (or 0), src = i (or 0)
    int dj = valid ? (int)j : 0;
    int si = valid ? i : 0;
    float3 dN = ldatom(X, dj, 0), dCA = ldatom(X, dj, 1), dC = ldatom(X, dj, 2);
    float3 sN = ldatom(X, si, 0), sCA = ldatom(X, si, 1), sC = ldatom(X, si, 2);
    float phi = dihedral4(dC, sN, sCA, sC);   // C_i, N_j, CA_j, C_j
    float psi = dihedral4(dN, dCA, dC, sN);   // N_i, CA_i, C_i, N_j
    out[offA + 2 * (size_t)e + 0] = valid ? phi : 0.0f;
    out[offA + 2 * (size_t)e + 1] = valid ? psi : 0.0f;
  }
}

// ---------------------------------------------------------------------------
// Generic fallback path for k != 10
// ---------------------------------------------------------------------------
__global__ void topk_generic_kernel(int N, int k, float* __restrict__ out,
                                    size_t offE, size_t offV) {
  int i = blockIdx.x * blockDim.x + threadIdx.x;
  if (i >= N) return;
  unsigned long long loc[KMAXG];
  for (int m = 0; m < k; m++) loc[m] = ~0ull;
  const float* row = g_dist + (size_t)i * N;
  for (int j = 0; j < N; j++) {
    unsigned long long key =
        ((unsigned long long)__float_as_uint(row[j]) << 32) | (unsigned int)j;
    if (key < loc[k - 1]) {
      loc[k - 1] = key;
      for (int m = k - 1; m > 0; m--) {
        if (loc[m] < loc[m - 1]) {
          unsigned long long tmp = loc[m];
          loc[m] = loc[m - 1];
          loc[m - 1] = tmp;
        }
      }
    }
  }
  for (int m = 0; m < k; m++) {
    unsigned long long key = loc[m];
    unsigned int j = (unsigned int)key;
    float v = __uint_as_float((unsigned int)(key >> 32));
    bool valid = (v < BIGF);
    int e = i * k + m;
    out[offE + e] = valid ? (float)j : -1.0f;
    out[offE + (size_t)N * k + e] = valid ? (float)i : -1.0f;
    out[offV + e] = valid ? 1.0f : 0.0f;
    g_dst[e] = valid ? (int)j : 0;
    g_src[e] = valid ? i : 0;
    g_val[e] = valid ? 1 : 0;
  }
}

__global__ void edge_attr_kernel(const float* __restrict__ X,
                                 float* __restrict__ out, size_t offA, int NE) {
  int e = blockIdx.x * blockDim.x + threadIdx.x;
  if (e >= NE) return;
  int dj = g_dst[e], si = g_src[e];
  float3 dN = ldatom(X, dj, 0), dCA = ldatom(X, dj, 1), dC = ldatom(X, dj, 2);
  float3 sN = ldatom(X, si, 0), sCA = ldatom(X, si, 1), sC = ldatom(X, si, 2);
  float phi = dihedral4(dC, sN, sCA, sC);
  float psi = dihedral4(dN, dCA, dC, sN);
  bool v = (g_val[e] != 0);
  out[offA + 2 * (size_t)e + 0] = v ? phi : 0.0f;
  out[offA + 2 * (size_t)e + 1] = v ? psi : 0.0f;
}

// ---------------------------------------------------------------------------
// Launcher. Output = concat(H[N,2E], edges[2,N*k], edge_attr[N*k,2], valid[N*k])
// ---------------------------------------------------------------------------
extern "C" void kernel_launch(void* const* d_in, const int* in_sizes, int n_in,
                              void* d_out, int out_size) {
  const float* X = (const float*)d_in[0];
  const int* S = (const int*)d_in[1];
  const int* RP = (const int*)d_in[2];
  const int* ID = (const int*)d_in[3];
  const int* Seg = (const int*)d_in[4];
  const int* bid = (const int*)d_in[5];
  const float* res_embed = (const float*)d_in[6];
  const float* id_embed = (const float*)d_in[7];
  float* out = (float*)d_out;

  int N = in_sizes[0] / 12;
  int E = in_sizes[7] / 2;
  long long rem = (long long)out_size - 2LL * E * N;
  int k = (int)(rem / (5LL * N));
  if (k < 1) k = 1;
  if (k > KMAXG) k = KMAXG;

  size_t offE = (size_t)N * 2 * E;
  size_t offA = offE + (size_t)2 * N * k;
  size_t offV = offA + (size_t)2 * N * k;

  node_feat_kernel<<<N, 2 * E>>>(res_embed, id_embed, S, RP, ID, out, N, E);

  dim3 dgrid((N + TJ - 1) / TJ, (N + TI - 1) / TI);
  dist_kernel<<<dgrid, 256>>>(X, Seg, bid, N);

  if (k == 10) {
    topk10_kernel<<<N, 32>>>(X, N, out, offE, offA, offV);
  } else {
    topk_generic_kernel<<<(N + 63) / 64, 64>>>(N, k, out, offE, offV);
    edge_attr_kernel<<<(N * k + 127) / 128, 128>>>(X, out, offA, N * k);
  }
}

// round 3
// speedup vs baseline: 1.6870x; 1.0033x over previous
#include <cuda_runtime.h>
#include <math.h>
#include <stdint.h>

#define BIGF 1e10f
#define NMAX 3072
#define KMAXG 64
#define TI 16
#define TJ 512
#define TJP 513

// Scratch (no allocations allowed).
__device__ float g_dist[(size_t)NMAX * NMAX];          // ~37.7 MB (L2-resident)
__device__ int g_dst[NMAX * KMAXG];
__device__ int g_src[NMAX * KMAXG];
__device__ unsigned char g_val[NMAX * KMAXG];

// ---------------------------------------------------------------------------
// Packed f32x2 helpers (Blackwell FFMA2 path — PTX only, ptxas won't auto-fuse)
// ---------------------------------------------------------------------------
static __device__ __forceinline__ unsigned long long pk2(float a, float b) {
  unsigned long long r;
  asm("mov.b64 %0, {%1,%2};" : "=l"(r) : "f"(a), "f"(b));
  return r;
}
static __device__ __forceinline__ void upk2(unsigned long long v, float& a, float& b) {
  asm("mov.b64 {%0,%1}, %2;" : "=f"(a), "=f"(b) : "l"(v));
}
static __device__ __forceinline__ unsigned long long fma2_(unsigned long long a,
                                                           unsigned long long b,
                                                           unsigned long long c) {
  unsigned long long r;
  asm("fma.rn.f32x2 %0, %1, %2, %3;" : "=l"(r) : "l"(a), "l"(b), "l"(c));
  return r;
}
static __device__ __forceinline__ unsigned long long mul2_(unsigned long long a,
                                                           unsigned long long b) {
  unsigned long long r;
  asm("mul.rn.f32x2 %0, %1, %2;" : "=l"(r) : "l"(a), "l"(b));
  return r;
}
static __device__ __forceinline__ unsigned long long add2_(unsigned long long a,
                                                           unsigned long long b) {
  unsigned long long r;
  asm("add.rn.f32x2 %0, %1, %2;" : "=l"(r) : "l"(a), "l"(b));
  return r;
}

// ---------------------------------------------------------------------------
// Kernel 1: node features. Block=128: t<E copies residue embedding; t in
// [E, E+E/2) computes one (sin,cos) pair with a single shared range reduction.
// ---------------------------------------------------------------------------
__global__ void node_feat_kernel(const float* __restrict__ res_embed,
                                 const float* __restrict__ id_embed,
                                 const int* __restrict__ S,
                                 const int* __restrict__ RP,
                                 const int* __restrict__ ID,
                                 float* __restrict__ out, int N, int E) {
  int i = blockIdx.x;
  int t = threadIdx.x;
  if (i >= N) return;
  float* orow = out + (size_t)i * (2 * E);
  if (t < E) {
    orow[t] = res_embed[S[i] * E + t];
  } else if (t < E + E / 2) {
    int p = t - E;                       // 0 .. E/2-1
    // freq = 10000^(-2p/E) = exp2(p * (-2*log2(10000)/E))
    float freq = exp2f((float)p * (-2.0f * 13.287712379549449f / (float)E));
    float ang = (float)RP[i] * freq;
    float s, c;
    sincosf(ang, &s, &c);
    const float* id = id_embed + ID[i] * E;
    orow[E + 2 * p] = s + id[2 * p];
    orow[E + 2 * p + 1] = c + id[2 * p + 1];
  }
}

// ---------------------------------------------------------------------------
// Kernel 2: symmetric masked pairwise min-channel distance, packed f32x2.
// Block = 16 i-rows x 512 j-cols (256 threads x 2 packed j). Computes only
// j >= i; mirrors the lower triangle through an smem transpose.
// ---------------------------------------------------------------------------
__global__ __launch_bounds__(256) void dist_kernel(const float* __restrict__ X,
                                                   const int* __restrict__ Seg,
                                                   const int* __restrict__ bid,
                                                   int N) {
  __shared__ unsigned long long sXip[TI][4][3];
  __shared__ unsigned long long sSicp[TI][4];
  __shared__ int sB[TI], sS[TI];
  __shared__ float sD[TI][TJP];

  int i0 = blockIdx.y * TI;
  int j0 = blockIdx.x * TJ;
  if (j0 + TJ - 1 < i0) return;  // tile fully below diagonal

  int t = threadIdx.x;
  if (t < TI * 4) {
    int r = t >> 2, c = t & 3;
    int gic = min(i0 + r, N - 1);
    const float* p = X + (size_t)gic * 12 + c * 3;
    float x = p[0], y = p[1], z = p[2];
    sXip[r][c][0] = pk2(x, x);
    sXip[r][c][1] = pk2(y, y);
    sXip[r][c][2] = pk2(z, z);
    float sic = x * x + y * y + z * z;
    sSicp[r][c] = pk2(sic, sic);
    if (c == 0) { sB[r] = bid[gic]; sS[r] = Seg[gic]; }
  }
  __syncthreads();

  int jA = j0 + 2 * t, jB = jA + 1;
  int jAc = min(jA, N - 1), jBc = min(jB, N - 1);
  const float4* pa = (const float4*)(X + (size_t)jAc * 12);
  const float4* pb = (const float4*)(X + (size_t)jBc * 12);
  float4 a0 = pa[0], a1 = pa[1], a2 = pa[2];
  float4 b0 = pb[0], b1 = pb[1], b2 = pb[2];
  float xa[12] = {a0.x, a0.y, a0.z, a0.w, a1.x, a1.y,
                  a1.z, a1.w, a2.x, a2.y, a2.z, a2.w};
  float xb[12] = {b0.x, b0.y, b0.z, b0.w, b1.x, b1.y,
                  b1.z, b1.w, b2.x, b2.y, b2.z, b2.w};
  unsigned long long xjp[4][3], sqjp[4];
#pragma unroll
  for (int e = 0; e < 4; e++) {
#pragma unroll
    for (int d = 0; d < 3; d++) xjp[e][d] = pk2(xa[e * 3 + d], xb[e * 3 + d]);
    sqjp[e] = fma2_(xjp[e][0], xjp[e][0],
                    fma2_(xjp[e][1], xjp[e][1], mul2_(xjp[e][2], xjp[e][2])));
  }
  int bidA = bid[jAc], segA = Seg[jAc];
  int bidB = bid[jBc], segB = Seg[jBc];
  const unsigned long long M2 = pk2(-2.0f, -2.0f);

  for (int r = 0; r < TI; r++) {
    int i = i0 + r;
    if (i >= N) break;
    if (jB < i) continue;  // both j strictly below diagonal: owned elsewhere
    float best0 = 3.4e38f, best1 = 3.4e38f;
#pragma unroll
    for (int c = 0; c < 4; c++) {
      unsigned long long xi0 = sXip[r][c][0];
      unsigned long long xi1 = sXip[r][c][1];
      unsigned long long xi2 = sXip[r][c][2];
      unsigned long long sic = sSicp[r][c];
#pragma unroll
      for (int e = 0; e < 4; e++) {
        unsigned long long dot =
            fma2_(xi0, xjp[e][0], fma2_(xi1, xjp[e][1], mul2_(xi2, xjp[e][2])));
        unsigned long long d2 = fma2_(dot, M2, add2_(sic, sqjp[e]));
        float d20, d21;
        upk2(d2, d20, d21);
        best0 = fminf(best0, d20);  // FMNMX -> alu pipe, overlaps fma pipe
        best1 = fminf(best1, d21);
      }
    }
    int bi_ = sB[r], si_ = sS[r];
    float d0 = (bi_ == bidA && si_ == segA) ? sqrtf(fmaxf(best0, 0.0f)) : BIGF;
    float d1 = (bi_ == bidB && si_ == segB) ? sqrtf(fmaxf(best1, 0.0f)) : BIGF;
    if (jA >= i && jA < N) g_dist[(size_t)i * N + jA] = d0;
    if (jB >= i && jB < N) g_dist[(size_t)i * N + jB] = d1;
    sD[r][2 * t] = d0;
    sD[r][2 * t + 1] = d1;
  }
  __syncthreads();

  // Mirror lower triangle: g_dist[j][i] = sD[i-i0][j-j0], predicate j > i.
  for (int idx = t; idx < TI * TJ; idx += 256) {
    int jr = idx >> 4;
    int rr = idx & 15;
    int j = j0 + jr, i = i0 + rr;
    if (j < N && i < N && j > i) g_dist[(size_t)j * N + i] = sD[rr][jr];
  }
}

// ---------------------------------------------------------------------------
// Dihedral helpers
// ---------------------------------------------------------------------------
__device__ __forceinline__ float3 ldatom(const float* __restrict__ X, int n, int c) {
  const float* p = X + (size_t)n * 12 + c * 3;
  return make_float3(p[0], p[1], p[2]);
}
__device__ __forceinline__ float3 f3sub(float3 a, float3 b) {
  return make_float3(a.x - b.x, a.y - b.y, a.z - b.z);
}
__device__ __forceinline__ float3 f3cross(float3 a, float3 b) {
  return make_float3(a.y * b.z - a.z * b.y, a.z * b.x - a.x * b.z,
                     a.x * b.y - a.y * b.x);
}
__device__ __forceinline__ float f3dot(float3 a, float3 b) {
  return a.x * b.x + a.y * b.y + a.z * b.z;
}
__device__ __forceinline__ float dihedral4(float3 a, float3 b, float3 c, float3 d) {
  float3 u1 = f3sub(b, a), u2 = f3sub(c, b), u3 = f3sub(d, c);
  float3 n1 = f3cross(u1, u2), n2 = f3cross(u2, u3);
  float nrm = sqrtf(f3dot(u2, u2)) + 1e-12f;
  float3 u2n = make_float3(u2.x / nrm, u2.y / nrm, u2.z / nrm);
  float3 m = f3cross(n1, u2n);
  return atan2f(f3dot(m, n2), f3dot(n1, n2));
}

// ---------------------------------------------------------------------------
// Kernel 3: top-10 per row (jax.lax.top_k tie semantics) + fused dihedrals.
// One warp per row; packed (dist_bits<<32 | j) keys. float4 scan with a
// 2-stage software pipeline for MLP.
// ---------------------------------------------------------------------------
__device__ __forceinline__ void tk_insert(unsigned long long* loc,
                                          unsigned long long key) {
  const int K = 10;
  if (key < loc[K - 1]) {
    loc[K - 1] = key;
#pragma unroll
    for (int m = K - 1; m > 0; m--) {
      if (loc[m] < loc[m - 1]) {
        unsigned long long tmp = loc[m];
        loc[m] = loc[m - 1];
        loc[m - 1] = tmp;
      }
    }
  }
}

__global__ void topk10_kernel(const float* __restrict__ X, int N,
                              float* __restrict__ out, size_t offE,
                              size_t offA, size_t offV) {
  const int K = 10;
  const int VW = 128;  // elements per warp per vector iter
  int i = blockIdx.x;
  int lane = threadIdx.x;
  const float* row = g_dist + (size_t)i * N;  // 16B-aligned (N*4*i % 16 == 0)

  unsigned long long loc[K];
#pragma unroll
  for (int m = 0; m < K; m++) loc[m] = ~0ull;

  int nvec = (N / VW) * VW;
  if (nvec > 0) {
    int j = lane * 4;
    float4 cur = *(const float4*)(row + j);
    for (int jb = 0; jb < nvec; jb += VW) {
      float4 nxt;
      int jn = jb + VW + lane * 4;
      if (jb + VW < nvec) nxt = *(const float4*)(row + jn);
      int jj = jb + lane * 4;
      tk_insert(loc, ((unsigned long long)__float_as_uint(cur.x) << 32) |
                         (unsigned int)(jj + 0));
      tk_insert(loc, ((unsigned long long)__float_as_uint(cur.y) << 32) |
                         (unsigned int)(jj + 1));
      tk_insert(loc, ((unsigned long long)__float_as_uint(cur.z) << 32) |
                         (unsigned int)(jj + 2));
      tk_insert(loc, ((unsigned long long)__float_as_uint(cur.w) << 32) |
                         (unsigned int)(jj + 3));
      cur = nxt;
    }
  }
  for (int j = nvec + lane; j < N; j += 32) {
    tk_insert(loc, ((unsigned long long)__float_as_uint(row[j]) << 32) |
                       (unsigned int)j);
  }

  __shared__ unsigned long long sh[32 * K];
#pragma unroll
  for (int m = 0; m < K; m++) sh[lane * K + m] = loc[m];
  __syncwarp();

  for (int h = 16; h >= 1; h >>= 1) {
    if (lane < h) {
      unsigned long long mg[K];
      int p = 0, q = 0;
#pragma unroll
      for (int m = 0; m < K; m++) {
        unsigned long long av = sh[lane * K + p];
        unsigned long long bv = sh[(lane + h) * K + q];
        if (av <= bv) { mg[m] = av; p++; }
        else          { mg[m] = bv; q++; }
      }
#pragma unroll
      for (int m = 0; m < K; m++) sh[lane * K + m] = mg[m];
    }
    __syncwarp();
  }

  if (lane < K) {
    unsigned long long key = sh[lane];
    unsigned int j = (unsigned int)key;
    float v = __uint_as_float((unsigned int)(key >> 32));
    bool valid = (v < BIGF);
    int e = i * K + lane;
    out[offE + e] = valid ? (float)j : -1.0f;                 // edges[0] (dst)
    out[offE + (size_t)N * K + e] = valid ? (float)i : -1.0f; // edges[1] (src)
    out[offV + e] = valid ? 1.0f : 0.0f;                      // valid mask

    // fused dihedrals: dst = max(edge,0) = j (or 0), src = i (or 0)
    int dj = valid ? (int)j : 0;
    int si = valid ? i : 0;
    float3 dN = ldatom(X, dj, 0), dCA = ldatom(X, dj, 1), dC = ldatom(X, dj, 2);
    float3 sN = ldatom(X, si, 0), sCA = ldatom(X, si, 1), sC = ldatom(X, si, 2);
    float phi = dihedral4(dC, sN, sCA, sC);   // C_i, N_j, CA_j, C_j
    float psi = dihedral4(dN, dCA, dC, sN);   // N_i, CA_i, C_i, N_j
    out[offA + 2 * (size_t)e + 0] = valid ? phi : 0.0f;
    out[offA + 2 * (size_t)e + 1] = valid ? psi : 0.0f;
  }
}

// ---------------------------------------------------------------------------
// Generic fallback path for k != 10
// ---------------------------------------------------------------------------
__global__ void topk_generic_kernel(int N, int k, float* __restrict__ out,
                                    size_t offE, size_t offV) {
  int i = blockIdx.x * blockDim.x + threadIdx.x;
  if (i >= N) return;
  unsigned long long loc[KMAXG];
  for (int m = 0; m < k; m++) loc[m] = ~0ull;
  const float* row = g_dist + (size_t)i * N;
  for (int j = 0; j < N; j++) {
    unsigned long long key =
        ((unsigned long long)__float_as_uint(row[j]) << 32) | (unsigned int)j;
    if (key < loc[k - 1]) {
      loc[k - 1] = key;
      for (int m = k - 1; m > 0; m--) {
        if (loc[m] < loc[m - 1]) {
          unsigned long long tmp = loc[m];
          loc[m] = loc[m - 1];
          loc[m - 1] = tmp;
        }
      }
    }
  }
  for (int m = 0; m < k; m++) {
    unsigned long long key = loc[m];
    unsigned int j = (unsigned int)key;
    float v = __uint_as_float((unsigned int)(key >> 32));
    bool valid = (v < BIGF);
    int e = i * k + m;
    out[offE + e] = valid ? (float)j : -1.0f;
    out[offE + (size_t)N * k + e] = valid ? (float)i : -1.0f;
    out[offV + e] = valid ? 1.0f : 0.0f;
    g_dst[e] = valid ? (int)j : 0;
    g_src[e] = valid ? i : 0;
    g_val[e] = valid ? 1 : 0;
  }
}

__global__ void edge_attr_kernel(const float* __restrict__ X,
                                 float* __restrict__ out, size_t offA, int NE) {
  int e = blockIdx.x * blockDim.x + threadIdx.x;
  if (e >= NE) return;
  int dj = g_dst[e], si = g_src[e];
  float3 dN = ldatom(X, dj, 0), dCA = ldatom(X, dj, 1), dC = ldatom(X, dj, 2);
  float3 sN = ldatom(X, si, 0), sCA = ldatom(X, si, 1), sC = ldatom(X, si, 2);
  float phi = dihedral4(dC, sN, sCA, sC);
  float psi = dihedral4(dN, dCA, dC, sN);
  bool v = (g_val[e] != 0);
  out[offA + 2 * (size_t)e + 0] = v ? phi : 0.0f;
  out[offA + 2 * (size_t)e + 1] = v ? psi : 0.0f;
}

// ---------------------------------------------------------------------------
// Launcher. Output = concat(H[N,2E], edges[2,N*k], edge_attr[N*k,2], valid[N*k])
// ---------------------------------------------------------------------------
extern "C" void kernel_launch(void* const* d_in, const int* in_sizes, int n_in,
                              void* d_out, int out_size) {
  const float* X = (const float*)d_in[0];
  const int* S = (const int*)d_in[1];
  const int* RP = (const int*)d_in[2];
  const int* ID = (const int*)d_in[3];
  const int* Seg = (const int*)d_in[4];
  const int* bid = (const int*)d_in[5];
  const float* res_embed = (const float*)d_in[6];
  const float* id_embed = (const float*)d_in[7];
  float* out = (float*)d_out;

  int N = in_sizes[0] / 12;
  int E = in_sizes[7] / 2;
  long long rem = (long long)out_size - 2LL * E * N;
  int k = (int)(rem / (5LL * N));
  if (k < 1) k = 1;
  if (k > KMAXG) k = KMAXG;

  size_t offE = (size_t)N * 2 * E;
  size_t offA = offE + (size_t)2 * N * k;
  size_t offV = offA + (size_t)2 * N * k;

  node_feat_kernel<<<N, 2 * E>>>(res_embed, id_embed, S, RP, ID, out, N, E);

  dim3 dgrid((N + TJ - 1) / TJ, (N + TI - 1) / TI);
  dist_kernel<<<dgrid, 256>>>(X, Seg, bid, N);

  if (k == 10) {
    topk10_kernel<<<N, 32>>>(X, N, out, offE, offA, offV);
  } else {
    topk_generic_kernel<<<(N + 63) / 64, 64>>>(N, k, out, offE, offV);
    edge_attr_kernel<<<(N * k + 127) / 128, 128>>>(X, out, offA, N * k);
  }
}